// round 15
// baseline (speedup 1.0000x reference)
#include <cuda_runtime.h>
#include <cuda_bf16.h>
#include <math.h>

#define BB   4
#define TT   1024
#define DD   1024
#define DIi  256
#define DCc  1280
#define DFFf 4096
#define HH   16
#define DHh  64
#define SSt  16
#define NNtk 256
#define EEx  1024
#define BT   (BB*TT)            /* 4096  */
#define BSN  (BB*SSt*NNtk)      /* 16384 */
#define NEGV -1e6f
#define FLW  36

// ---------------- scratch ----------------
__device__ float g_q[BT*DD];
__device__ float g_k[BT*DD];
__device__ float g_v[BT*DD];
__device__ float g_merged[BT*DD];
__device__ float g_x2[BT*DD];
__device__ float g_y[BT*DD];
__device__ float g_yi[BT*DCc];
__device__ float g_qs[BT*DD];
__device__ float g_qt[BT*DD];
__device__ float g_ksf[BB*SSt*DD];
__device__ float g_kt[(size_t)BSN*DD];
__device__ float g_vv[(size_t)BSN*DD];
__device__ float g_tsc[(size_t)BT*SSt*NNtk];
__device__ float g_ssc[BT*SSt];
__device__ int   g_selidx[BT*128];
__device__ float g_selw[BT*128];
__device__ int   g_selcnt[BT];
__device__ float g_y2s_raw[BT*DD];
__device__ float g_y2s[BT*DD];
__device__ float g_y2e[BT*DD];
__device__ float g_y2[BT*DD];
__device__ float g_z[BT*DD];
__device__ float g_ffh[(size_t)BT*DFFf];
__device__ float g_ffo[BT*DD];

// ---------------- helpers ----------------
__device__ __forceinline__ void mma_bf16(float c[4], const unsigned a[4], unsigned b0, unsigned b1){
    asm volatile("mma.sync.aligned.m16n8k16.row.col.f32.bf16.bf16.f32 "
        "{%0,%1,%2,%3},{%4,%5,%6,%7},{%8,%9},{%0,%1,%2,%3};\n"
        : "+f"(c[0]), "+f"(c[1]), "+f"(c[2]), "+f"(c[3])
        : "r"(a[0]), "r"(a[1]), "r"(a[2]), "r"(a[3]), "r"(b0), "r"(b1));
}
__device__ __forceinline__ void split_bf2(float a, float b, unsigned& hi, unsigned& lo){
    __nv_bfloat16 ha = __float2bfloat16(a);
    __nv_bfloat16 hb = __float2bfloat16(b);
    __nv_bfloat16 la = __float2bfloat16(a - __bfloat162float(ha));
    __nv_bfloat16 lb = __float2bfloat16(b - __bfloat162float(hb));
    hi = (unsigned)__bfloat16_as_ushort(ha) | ((unsigned)__bfloat16_as_ushort(hb) << 16);
    lo = (unsigned)__bfloat16_as_ushort(la) | ((unsigned)__bfloat16_as_ushort(lb) << 16);
}
__device__ __forceinline__ void split_bf1(float a, unsigned short& hi, unsigned short& lo){
    __nv_bfloat16 h = __float2bfloat16(a);
    __nv_bfloat16 l = __float2bfloat16(a - __bfloat162float(h));
    hi = __bfloat16_as_ushort(h);
    lo = __bfloat16_as_ushort(l);
}
__device__ __forceinline__ float warpRedSum(float v){
#pragma unroll
    for (int o = 16; o > 0; o >>= 1) v += __shfl_xor_sync(0xffffffffu, v, o);
    return v;
}
__device__ __forceinline__ float blockSum(float v, float* sh){
    int lane = threadIdx.x & 31, w = threadIdx.x >> 5;
    v = warpRedSum(v);
    if (lane == 0) sh[w] = v;
    __syncthreads();
    if (w == 0){
        int nw = blockDim.x >> 5;
        float r = (lane < nw) ? sh[lane] : 0.f;
        r = warpRedSum(r);
        if (lane == 0) sh[0] = r;
    }
    __syncthreads();
    float r = sh[0];
    __syncthreads();
    return r;
}

// ================= fused flash attention (3xBF16 QK^T and PV) =================
template<bool CAUSAL>
__global__ void __launch_bounds__(256)
flash_kernel(const float* __restrict__ Qg, const float* __restrict__ Kg,
             const float* __restrict__ Vg, float* __restrict__ Og,
             int Tk, const int* __restrict__ evl, float scale)
{
    extern __shared__ unsigned sm[];
    unsigned* QH = sm;
    unsigned* QL = sm + 4608;
    unsigned* KH = sm + 9216;
    unsigned* KL = sm + 11520;
    unsigned* VH = sm + 13824;
    unsigned* VL = sm + 16128;
    unsigned* PH = sm + 18432;
    unsigned* PL = sm + 23040;
    float* m_s  = (float*)(sm + 27648);
    float* l_s  = (float*)(sm + 27776);
    float* al_s = (float*)(sm + 27904);
    float* red0 = (float*)(sm + 28032);
    float* red1 = (float*)(sm + 28288);

    int bh = blockIdx.y;
    int b = bh / HH, h = bh % HH;
    int q0 = blockIdx.x * 128;
    const float* Qb = Qg + (size_t)b*TT*DD + h*DHh;
    const float* Kb = Kg + (size_t)b*Tk*DD + h*DHh;
    const float* Vb = Vg + (size_t)b*Tk*DD + h*DHh;
    float*       Ob = Og + (size_t)b*TT*DD + h*DHh;

    int tid = threadIdx.x, lane = tid & 31, wid = tid >> 5;
    int wm = wid >> 1, wn = wid & 1;
    int g = lane >> 2, tg = lane & 3;

#pragma unroll
    for (int v = 0; v < 8; v++){
        int idx = tid + v*256;
        int r = idx >> 4, f4 = idx & 15;
        float4 qv = *(const float4*)(Qb + (size_t)(q0+r)*DD + f4*4);
        split_bf2(qv.x, qv.y, QH[r*FLW + f4*2],   QL[r*FLW + f4*2]);
        split_bf2(qv.z, qv.w, QH[r*FLW + f4*2+1], QL[r*FLW + f4*2+1]);
    }
    if (tid < 128){ m_s[tid] = -1e30f; l_s[tid] = 0.f; }

    float oacc[2][4][4] = {};

    int vl = CAUSAL ? Tk : evl[b];
    int nkt = CAUSAL ? (q0/64 + 2) : ((vl + 63) >> 6);

    __syncthreads();

    for (int kt = 0; kt < nkt; kt++){
        int k0 = kt * 64;
#pragma unroll
        for (int v = 0; v < 4; v++){
            int idx = tid + v*256;
            int r = idx >> 4, f4 = idx & 15;
            float4 kv = *(const float4*)(Kb + (size_t)(k0+r)*DD + f4*4);
            split_bf2(kv.x, kv.y, KH[r*FLW + f4*2],   KL[r*FLW + f4*2]);
            split_bf2(kv.z, kv.w, KH[r*FLW + f4*2+1], KL[r*FLW + f4*2+1]);
            float4 vv = *(const float4*)(Vb + (size_t)(k0+r)*DD + f4*4);
            float fv[4] = {vv.x, vv.y, vv.z, vv.w};
#pragma unroll
            for (int j = 0; j < 4; j++){
                unsigned short hh, ll;
                split_bf1(fv[j], hh, ll);
                int col = f4*4 + j;
                ((unsigned short*)&VH[col*FLW + (r>>1)])[r&1] = hh;
                ((unsigned short*)&VL[col*FLW + (r>>1)])[r&1] = ll;
            }
        }
        __syncthreads();

        float sacc[2][4][4] = {};
#pragma unroll
        for (int ks = 0; ks < 4; ks++){
            unsigned aH[2][4], aL[2][4];
#pragma unroll
            for (int mt = 0; mt < 2; mt++){
                int mr = wm*32 + mt*16;
                aH[mt][0] = QH[(mr+g)*FLW + ks*8+tg];
                aH[mt][1] = QH[(mr+g+8)*FLW + ks*8+tg];
                aH[mt][2] = QH[(mr+g)*FLW + ks*8+4+tg];
                aH[mt][3] = QH[(mr+g+8)*FLW + ks*8+4+tg];
                aL[mt][0] = QL[(mr+g)*FLW + ks*8+tg];
                aL[mt][1] = QL[(mr+g+8)*FLW + ks*8+tg];
                aL[mt][2] = QL[(mr+g)*FLW + ks*8+4+tg];
                aL[mt][3] = QL[(mr+g+8)*FLW + ks*8+4+tg];
            }
#pragma unroll
            for (int nt = 0; nt < 4; nt++){
                int nc = wn*32 + nt*8;
                unsigned bh0 = KH[(nc+g)*FLW + ks*8+tg];
                unsigned bh1 = KH[(nc+g)*FLW + ks*8+4+tg];
                unsigned bl0 = KL[(nc+g)*FLW + ks*8+tg];
                unsigned bl1 = KL[(nc+g)*FLW + ks*8+4+tg];
#pragma unroll
                for (int mt = 0; mt < 2; mt++){
                    mma_bf16(sacc[mt][nt], aH[mt], bl0, bl1);
                    mma_bf16(sacc[mt][nt], aL[mt], bh0, bh1);
                    mma_bf16(sacc[mt][nt], aH[mt], bh0, bh1);
                }
            }
        }

        float rmax[2][2] = {{-1e30f,-1e30f},{-1e30f,-1e30f}};
#pragma unroll
        for (int mt = 0; mt < 2; mt++){
            int r0 = q0 + wm*32 + mt*16 + g;
#pragma unroll
            for (int nt = 0; nt < 4; nt++){
                int c0 = k0 + wn*32 + nt*8 + 2*tg;
#pragma unroll
                for (int i = 0; i < 4; i++){
                    int rr = r0 + ((i>=2)?8:0);
                    int cc = c0 + (i&1);
                    bool ok = CAUSAL ? (cc <= rr) : (cc < vl);
                    float sv = ok ? sacc[mt][nt][i]*scale : -1e30f;
                    sacc[mt][nt][i] = sv;
                    rmax[mt][i>>1] = fmaxf(rmax[mt][i>>1], sv);
                }
            }
#pragma unroll
            for (int hf = 0; hf < 2; hf++){
                float v = rmax[mt][hf];
                v = fmaxf(v, __shfl_xor_sync(0xffffffffu, v, 1));
                v = fmaxf(v, __shfl_xor_sync(0xffffffffu, v, 2));
                rmax[mt][hf] = v;
            }
        }
        if (tg == 0){
#pragma unroll
            for (int mt = 0; mt < 2; mt++){
                red0[wn*128 + wm*32 + mt*16 + g]     = rmax[mt][0];
                red0[wn*128 + wm*32 + mt*16 + g + 8] = rmax[mt][1];
            }
        }
        __syncthreads();
        if (tid < 128){
            float t = fmaxf(red0[tid], red0[128+tid]);
            float mo = m_s[tid];
            float mn = fmaxf(mo, t);
            al_s[tid] = __expf(mo - mn);
            m_s[tid] = mn;
        }
        __syncthreads();

        float rsum[2][2] = {};
#pragma unroll
        for (int mt = 0; mt < 2; mt++){
            int lr0 = wm*32 + mt*16 + g;
            float mn0 = m_s[lr0], mn1 = m_s[lr0+8];
#pragma unroll
            for (int nt = 0; nt < 4; nt++){
                float p0 = __expf(sacc[mt][nt][0] - mn0);
                float p1 = __expf(sacc[mt][nt][1] - mn0);
                float p2 = __expf(sacc[mt][nt][2] - mn1);
                float p3 = __expf(sacc[mt][nt][3] - mn1);
                rsum[mt][0] += p0 + p1;
                rsum[mt][1] += p2 + p3;
                int w0 = wn*16 + nt*4 + tg;
                split_bf2(p0, p1, PH[lr0*FLW + w0],     PL[lr0*FLW + w0]);
                split_bf2(p2, p3, PH[(lr0+8)*FLW + w0], PL[(lr0+8)*FLW + w0]);
            }
#pragma unroll
            for (int hf = 0; hf < 2; hf++){
                float v = rsum[mt][hf];
                v += __shfl_xor_sync(0xffffffffu, v, 1);
                v += __shfl_xor_sync(0xffffffffu, v, 2);
                rsum[mt][hf] = v;
            }
            float a0 = al_s[lr0], a1 = al_s[lr0+8];
#pragma unroll
            for (int nt = 0; nt < 4; nt++){
                oacc[mt][nt][0] *= a0; oacc[mt][nt][1] *= a0;
                oacc[mt][nt][2] *= a1; oacc[mt][nt][3] *= a1;
            }
        }
        if (tg == 0){
#pragma unroll
            for (int mt = 0; mt < 2; mt++){
                red1[wn*128 + wm*32 + mt*16 + g]     = rsum[mt][0];
                red1[wn*128 + wm*32 + mt*16 + g + 8] = rsum[mt][1];
            }
        }
        __syncthreads();
        if (tid < 128)
            l_s[tid] = l_s[tid]*al_s[tid] + red1[tid] + red1[128+tid];

#pragma unroll
        for (int ks = 0; ks < 4; ks++){
            unsigned aH[2][4], aL[2][4];
#pragma unroll
            for (int mt = 0; mt < 2; mt++){
                int mr = wm*32 + mt*16;
                aH[mt][0] = PH[(mr+g)*FLW + ks*8+tg];
                aH[mt][1] = PH[(mr+g+8)*FLW + ks*8+tg];
                aH[mt][2] = PH[(mr+g)*FLW + ks*8+4+tg];
                aH[mt][3] = PH[(mr+g+8)*FLW + ks*8+4+tg];
                aL[mt][0] = PL[(mr+g)*FLW + ks*8+tg];
                aL[mt][1] = PL[(mr+g+8)*FLW + ks*8+tg];
                aL[mt][2] = PL[(mr+g)*FLW + ks*8+4+tg];
                aL[mt][3] = PL[(mr+g+8)*FLW + ks*8+4+tg];
            }
#pragma unroll
            for (int nt = 0; nt < 4; nt++){
                int nc = wn*32 + nt*8;
                unsigned bh0 = VH[(nc+g)*FLW + ks*8+tg];
                unsigned bh1 = VH[(nc+g)*FLW + ks*8+4+tg];
                unsigned bl0 = VL[(nc+g)*FLW + ks*8+tg];
                unsigned bl1 = VL[(nc+g)*FLW + ks*8+4+tg];
#pragma unroll
                for (int mt = 0; mt < 2; mt++){
                    mma_bf16(oacc[mt][nt], aH[mt], bl0, bl1);
                    mma_bf16(oacc[mt][nt], aL[mt], bh0, bh1);
                    mma_bf16(oacc[mt][nt], aH[mt], bh0, bh1);
                }
            }
        }
        __syncthreads();
    }

#pragma unroll
    for (int mt = 0; mt < 2; mt++){
        int lr0 = wm*32 + mt*16 + g;
        float il0 = 1.f / l_s[lr0];
        float il1 = 1.f / l_s[lr0+8];
#pragma unroll
        for (int nt = 0; nt < 4; nt++){
            int c = wn*32 + nt*8 + 2*tg;
            Ob[(size_t)(q0+lr0)*DD + c]     = oacc[mt][nt][0]*il0;
            Ob[(size_t)(q0+lr0)*DD + c+1]   = oacc[mt][nt][1]*il0;
            Ob[(size_t)(q0+lr0+8)*DD + c]   = oacc[mt][nt][2]*il1;
            Ob[(size_t)(q0+lr0+8)*DD + c+1] = oacc[mt][nt][3]*il1;
        }
    }
}

// ===== 3xBF16 GEMM, 2-stage ping-pong, BK=32 (96 MMAs per barrier round) ========
template<int BM, int BN, bool TRANSB>
__global__ void __launch_bounds__((BM/64)*(BN/32)*32, 2)
gemm_bf16(const float* __restrict__ A, const float* __restrict__ B, float* __restrict__ C,
          int M, int N, int K, int lda, int ldb, int ldc, int NH,
          size_t sAb, size_t sAh, size_t sBb, size_t sBh, size_t sCb, size_t sCh,
          const float* __restrict__ bias, float scale, int act)
{
    constexpr int NWN = BN/32, NWM = BM/64, NW = NWN*NWM, NTH = NW*32;
    constexpr int BKb = 32;
    constexpr int AV  = (BM*BKb/4)/NTH;                 // 4
    constexpr int BV  = (TRANSB ? BN*BKb/4 : (BKb*BN/4))/NTH;  // 4
    constexpr int AW  = 20;                             // 16 payload bf16x2 words + 4 pad
    constexpr int ASZ = BM*AW;
    constexpr int BSZ = BN*AW;

    extern __shared__ unsigned dsm[];
    unsigned* AsH = dsm;
    unsigned* AsL = dsm + 2*ASZ;
    unsigned* BsH = dsm + 4*ASZ;
    unsigned* BsL = dsm + 4*ASZ + 2*BSZ;

    int z = blockIdx.z;
    const float* Ab = A + (size_t)(z/NH)*sAb + (size_t)(z%NH)*sAh;
    const float* Bb = B + (size_t)(z/NH)*sBb + (size_t)(z%NH)*sBh;
    float*       Cb = C + (size_t)(z/NH)*sCb + (size_t)(z%NH)*sCh;

    int tid = threadIdx.x, lane = tid & 31, wid = tid >> 5;
    int wn = wid % NWN, wm = wid / NWN;
    int row0 = blockIdx.y * BM, col0 = blockIdx.x * BN;
    int g = lane >> 2, tg = lane & 3;

    float acc[4][4][4] = {};
    float4 ra[AV], rb[BV];

    auto fetchA = [&](int kk){
#pragma unroll
        for (int v = 0; v < AV; v++){
            int i = tid + v*NTH;
            int r = i >> 3, c = (i & 7) * 4;
            int gr = row0 + r;
            ra[v] = (gr < M) ? *(const float4*)(Ab + (size_t)gr*lda + kk + c)
                             : make_float4(0.f,0.f,0.f,0.f);
        }
    };
    auto storeA = [&](int st){
        unsigned* aH = AsH + st*ASZ;
        unsigned* aL = AsL + st*ASZ;
#pragma unroll
        for (int v = 0; v < AV; v++){
            int i = tid + v*NTH;
            int r = i >> 3, c2 = (i & 7) * 2;
            split_bf2(ra[v].x, ra[v].y, aH[r*AW+c2],   aL[r*AW+c2]);
            split_bf2(ra[v].z, ra[v].w, aH[r*AW+c2+1], aL[r*AW+c2+1]);
        }
    };
    auto fetchB = [&](int kk){
        if (TRANSB){
#pragma unroll
            for (int v = 0; v < BV; v++){
                int i = tid + v*NTH;
                int r = i >> 3, c = (i & 7) * 4;
                int gr = col0 + r;
                rb[v] = (gr < N) ? *(const float4*)(Bb + (size_t)gr*ldb + kk + c)
                                 : make_float4(0.f,0.f,0.f,0.f);
            }
        } else {
            constexpr int VPR = BN/4;
#pragma unroll
            for (int v = 0; v < BV; v++){
                int i = tid + v*NTH;
                int r = i / VPR, c = (i % VPR) * 4;
                int gc = col0 + c;
                rb[v] = (gc < N) ? *(const float4*)(Bb + (size_t)(kk+r)*ldb + gc)
                                 : make_float4(0.f,0.f,0.f,0.f);
            }
        }
    };
    auto storeB = [&](int st){
        unsigned* bH = BsH + st*BSZ;
        unsigned* bL = BsL + st*BSZ;
        if (TRANSB){
#pragma unroll
            for (int v = 0; v < BV; v++){
                int i = tid + v*NTH;
                int r = i >> 3, c2 = (i & 7) * 2;
                split_bf2(rb[v].x, rb[v].y, bH[r*AW+c2],   bL[r*AW+c2]);
                split_bf2(rb[v].z, rb[v].w, bH[r*AW+c2+1], bL[r*AW+c2+1]);
            }
        } else {
            constexpr int VPR = BN/4;
#pragma unroll
            for (int v = 0; v < BV; v++){
                int i = tid + v*NTH;
                int r = i / VPR, c = (i % VPR) * 4;  // r = k row (0..31), c = n col
                float f[4] = {rb[v].x, rb[v].y, rb[v].z, rb[v].w};
#pragma unroll
                for (int j = 0; j < 4; j++){
                    unsigned short h, l;
                    split_bf1(f[j], h, l);
                    ((unsigned short*)&bH[(c+j)*AW + (r>>1)])[r&1] = h;
                    ((unsigned short*)&bL[(c+j)*AW + (r>>1)])[r&1] = l;
                }
            }
        }
    };

    fetchA(0); fetchB(0);
    storeA(0); storeB(0);
    __syncthreads();

    int kiters = K / BKb;
    for (int kt = 0; kt < kiters; kt++){
        int st = kt & 1;
        bool more = (kt + 1 < kiters);
        if (more){ fetchA((kt+1)*BKb); fetchB((kt+1)*BKb); }
        const unsigned* aH = AsH + st*ASZ;
        const unsigned* aL = AsL + st*ASZ;
        const unsigned* bHs = BsH + st*BSZ;
        const unsigned* bLs = BsL + st*BSZ;
#pragma unroll
        for (int ks = 0; ks < 2; ks++){
            int ko = ks * 8;
            unsigned afH[4][4], afL[4][4];
#pragma unroll
            for (int mt = 0; mt < 4; mt++){
                int mr = wm*64 + mt*16;
                afH[mt][0] = aH[(mr+g  )*AW + ko+tg  ];
                afH[mt][1] = aH[(mr+g+8)*AW + ko+tg  ];
                afH[mt][2] = aH[(mr+g  )*AW + ko+tg+4];
                afH[mt][3] = aH[(mr+g+8)*AW + ko+tg+4];
                afL[mt][0] = aL[(mr+g  )*AW + ko+tg  ];
                afL[mt][1] = aL[(mr+g+8)*AW + ko+tg  ];
                afL[mt][2] = aL[(mr+g  )*AW + ko+tg+4];
                afL[mt][3] = aL[(mr+g+8)*AW + ko+tg+4];
            }
#pragma unroll
            for (int nt = 0; nt < 4; nt++){
                int nc = wn*32 + nt*8;
                unsigned bh0 = bHs[(nc+g)*AW + ko+tg], bh1 = bHs[(nc+g)*AW + ko+tg+4];
                unsigned bl0 = bLs[(nc+g)*AW + ko+tg], bl1 = bLs[(nc+g)*AW + ko+tg+4];
#pragma unroll
                for (int mt = 0; mt < 4; mt++){
                    mma_bf16(acc[mt][nt], afH[mt], bl0, bl1);
                    mma_bf16(acc[mt][nt], afL[mt], bh0, bh1);
                    mma_bf16(acc[mt][nt], afH[mt], bh0, bh1);
                }
            }
        }
        if (more){
            storeA(st ^ 1); storeB(st ^ 1);
            __syncthreads();
        }
    }

#pragma unroll
    for (int mt = 0; mt < 4; mt++){
#pragma unroll
        for (int nt = 0; nt < 4; nt++){
            int r  = row0 + wm*64 + mt*16 + g;
            int c  = col0 + wn*32 + nt*8 + 2*tg;
            float b0 = bias ? bias[c]   : 0.f;
            float b1 = bias ? bias[c+1] : 0.f;
            if (r < M && c < N){
                float v0 = acc[mt][nt][0]*scale + b0;
                float v1 = acc[mt][nt][1]*scale + b1;
                if (act){ v0 = fmaxf(v0,0.f); v1 = fmaxf(v1,0.f); }
                Cb[(size_t)r*ldc + c]   = v0;
                Cb[(size_t)r*ldc + c+1] = v1;
            }
            int r2 = r + 8;
            if (r2 < M && c < N){
                float v2 = acc[mt][nt][2]*scale + b0;
                float v3 = acc[mt][nt][3]*scale + b1;
                if (act){ v2 = fmaxf(v2,0.f); v3 = fmaxf(v3,0.f); }
                Cb[(size_t)r2*ldc + c]   = v2;
                Cb[(size_t)r2*ldc + c+1] = v3;
            }
        }
    }
}

// ---------------- LN ----------------
__global__ void ln_kernel(const float* __restrict__ A, const float* __restrict__ Bm, float sB,
                          const float* __restrict__ gw, const float* __restrict__ bw,
                          float* __restrict__ Out)
{
    __shared__ float sh[32];
    int row = blockIdx.x;
    int tid = threadIdx.x;
    float4 a4 = *(const float4*)(A + (size_t)row*DD + tid*4);
    float x[4] = {a4.x, a4.y, a4.z, a4.w};
    if (Bm){
        float4 b4 = *(const float4*)(Bm + (size_t)row*DD + tid*4);
        x[0] += sB*b4.x; x[1] += sB*b4.y; x[2] += sB*b4.z; x[3] += sB*b4.w;
    }
    float s = x[0]+x[1]+x[2]+x[3];
    s = blockSum(s, sh);
    float mean = s * (1.f/DD);
    float q = 0.f;
#pragma unroll
    for (int i = 0; i < 4; i++){ float d = x[i]-mean; q += d*d; }
    q = blockSum(q, sh);
    float rstd = rsqrtf(q * (1.f/DD) + 1e-5f);
#pragma unroll
    for (int i = 0; i < 4; i++){
        int c = tid*4 + i;
        Out[(size_t)row*DD + c] = (x[i]-mean)*rstd*gw[c] + bw[c];
    }
}

// ---------------- concat ----------------
__global__ void concat_kernel(const float* __restrict__ Y, const float* __restrict__ intent,
                              float* __restrict__ Yi)
{
    int i = blockIdx.x*blockDim.x + threadIdx.x;
    if (i >= BT*DCc) return;
    int row = i / DCc, c = i % DCc;
    float val;
    if (c < DD) val = Y[(size_t)row*DD + c];
    else { int b = row / TT; val = intent[b*DIi + (c - DD)]; }
    Yi[i] = val;
}

// ---------------- ssc ----------------
__global__ void ssc_kernel(const float* __restrict__ QS, const float* __restrict__ KS,
                           float* __restrict__ SSC)
{
    __shared__ float qsh[DD];
    int row = blockIdx.x;
    int b = row / TT;
    int tid = threadIdx.x;
    *(float4*)&qsh[tid*4] = *(const float4*)(QS + (size_t)row*DD + tid*4);
    __syncthreads();
    int w = tid >> 5, lane = tid & 31;
    for (int ss = w; ss < SSt; ss += 8){
        const float* kr = KS + ((size_t)b*SSt + ss)*DD;
        float sum = 0.f;
        for (int j = lane*4; j < DD; j += 128){
            float4 kv = *(const float4*)(kr + j);
            float4 qv = *(const float4*)&qsh[j];
            sum += qv.x*kv.x + qv.y*kv.y + qv.z*kv.z + qv.w*kv.w;
        }
        sum = warpRedSum(sum);
        if (lane == 0) SSC[row*SSt + ss] = sum * (1.f/32.f);
    }
}

// ---------------- topk select ----------------
__global__ void sel_topk_kernel(const float* __restrict__ SSC, const float* __restrict__ TSC,
                                const int* __restrict__ svl,
                                int* __restrict__ OutIdx, float* __restrict__ OutW,
                                int* __restrict__ OutCnt)
{
    __shared__ float s_v[SSt];
    __shared__ float s_sw[SSt];
    __shared__ int   s_rank[SSt];
    __shared__ float s_tv[SSt][16];
    __shared__ int   s_ti[SSt][16];
    int row = blockIdx.x;
    int b = row / TT;
    int tid = threadIdx.x;
    int w = tid >> 5, lane = tid & 31;
    if (tid < SSt){
        float val = SSC[row*SSt + tid];
        if (tid >= svl[b]) val = NEGV;
        s_v[tid] = val;
    }
    __syncthreads();
    if (tid < SSt){
        float myv = s_v[tid];
        int cnt = 0;
        float m = -3.4e38f;
#pragma unroll
        for (int j = 0; j < SSt; j++){
            float o = s_v[j];
            if (o > myv || (o == myv && j < tid)) cnt++;
            m = fmaxf(m, o);
        }
        s_sw[tid] = (cnt < 8) ? expf(myv - m) : 0.f;
    }
    __syncthreads();
    if (tid == 0){
        float den = 0.f;
        for (int j = 0; j < SSt; j++) den += s_sw[j];
        float inv = 1.f/den;
        int r = 0;
        for (int j = 0; j < SSt; j++){
            float swv = s_sw[j]*inv;
            s_sw[j] = swv;
            s_rank[j] = r;
            if (swv > 0.f) r++;
        }
        OutCnt[row] = r*16;
    }
    __syncthreads();
    float swv = s_sw[w];
    if (swv > 0.f){
        const float* tr = TSC + ((size_t)row*SSt + w)*NNtk;
        float vloc[8];
#pragma unroll
        for (int r2 = 0; r2 < 8; r2++) vloc[r2] = tr[r2*32 + lane];
        for (int it = 0; it < 16; it++){
            float bv = -3.4e38f; int bi = 1 << 30;
#pragma unroll
            for (int r2 = 0; r2 < 8; r2++){
                if (vloc[r2] > bv){ bv = vloc[r2]; bi = r2*32 + lane; }
            }
#pragma unroll
            for (int off = 16; off > 0; off >>= 1){
                float ov = __shfl_xor_sync(0xffffffffu, bv, off);
                int   oi = __shfl_xor_sync(0xffffffffu, bi, off);
                if (ov > bv || (ov == bv && oi < bi)){ bv = ov; bi = oi; }
            }
            if (lane == 0){ s_tv[w][it] = bv; s_ti[w][it] = bi; }
            if ((bi & 31) == lane) vloc[bi >> 5] = -3.4e38f;
        }
        __syncwarp();
        float m2 = s_tv[w][0];
        float e2 = (lane < 16) ? expf(s_tv[w][lane] - m2) : 0.f;
        float den2 = warpRedSum(e2);
        if (lane < 16){
            int base = s_rank[w]*16;
            OutW[row*128 + base + lane]   = swv * e2 / den2;
            OutIdx[row*128 + base + lane] = w*NNtk + s_ti[w][lane];
        }
    }
}

// ---------------- sparse gather y2s ----------------
__global__ void gather_y2s_kernel(const int* __restrict__ Idx, const float* __restrict__ Wt,
                                  const int* __restrict__ Cnt, const float* __restrict__ VV,
                                  float* __restrict__ Out)
{
    __shared__ int   sh_i[128];
    __shared__ float sh_w[128];
    int row = blockIdx.x;
    int b = row / TT;
    int tid = threadIdx.x;
    int cnt = Cnt[row];
    if (tid < 128){ sh_i[tid] = Idx[row*128 + tid]; sh_w[tid] = Wt[row*128 + tid]; }
    __syncthreads();
    const float* vb = VV + (size_t)b*SSt*NNtk*DD;
    float4 acc = make_float4(0.f,0.f,0.f,0.f);
    int c4 = tid*4;
    for (int e = 0; e < cnt; e++){
        float wv = sh_w[e];
        float4 x4 = *(const float4*)(vb + (size_t)sh_i[e]*DD + c4);
        acc.x += wv*x4.x; acc.y += wv*x4.y; acc.z += wv*x4.z; acc.w += wv*x4.w;
    }
    *(float4*)(Out + (size_t)row*DD + c4) = acc;
}

// ---------------- gate ----------------
__global__ void gate_kernel(const float* __restrict__ Y2S, const float* __restrict__ Y2E,
                            const float* __restrict__ Wg, float* __restrict__ Y2)
{
    __shared__ float sh[32];
    int row = blockIdx.x;
    int tid = threadIdx.x;
    int c4 = tid*4;
    float4 a  = *(const float4*)(Y2S + (size_t)row*DD + c4);
    float4 b4 = *(const float4*)(Y2E + (size_t)row*DD + c4);
    float4 w1 = *(const float4*)(Wg + c4);
    float4 w2 = *(const float4*)(Wg + DD + c4);
    float part = a.x*w1.x + a.y*w1.y + a.z*w1.z + a.w*w1.w
               + b4.x*w2.x + b4.y*w2.y + b4.z*w2.z + b4.w*w2.w;
    float dot = blockSum(part, sh);
    float gv = 1.f/(1.f + expf(-dot));
    float4 o;
    o.x = gv*a.x + (1.f-gv)*b4.x;
    o.y = gv*a.y + (1.f-gv)*b4.y;
    o.z = gv*a.z + (1.f-gv)*b4.z;
    o.w = gv*a.w + (1.f-gv)*b4.w;
    *(float4*)(Y2 + (size_t)row*DD + c4) = o;
}

// ---------------- launch ----------------
extern "C" void kernel_launch(void* const* d_in, const int* in_sizes, int n_in,
                              void* d_out, int out_size)
{
    const float* x        = (const float*)d_in[0];
    const float* stat_enc = (const float*)d_in[1];
    const float* ex       = (const float*)d_in[2];
    const float* stat_ft  = (const float*)d_in[3];
    const float* intent   = (const float*)d_in[4];
    const float* Wq1=(const float*)d_in[5],  *Wk1=(const float*)d_in[6];
    const float* Wv1=(const float*)d_in[7],  *Wo1=(const float*)d_in[8];
    const float* Wq_stat=(const float*)d_in[9],  *Wq_token=(const float*)d_in[10];
    const float* Wk_stat=(const float*)d_in[11], *Wk_token=(const float*)d_in[12];
    const float* Wv_sel=(const float*)d_in[13],  *Wo_sel=(const float*)d_in[14];
    const float* Wq2=(const float*)d_in[15], *Wk2=(const float*)d_in[16];
    const float* Wv2=(const float*)d_in[17], *Wo2=(const float*)d_in[18];
    const float* Wg=(const float*)d_in[19];
    const float* W1=(const float*)d_in[20], *b1=(const float*)d_in[21];
    const float* W2=(const float*)d_in[22], *b2=(const float*)d_in[23];
    const float* w_g1=(const float*)d_in[24], *w_be1=(const float*)d_in[25];
    const float* w_g2=(const float*)d_in[26], *w_be2=(const float*)d_in[27];
    const float* w_g3=(const float*)d_in[28], *w_be3=(const float*)d_in[29];
    const int* svl = (const int*)d_in[30];
    const int* evl = (const int*)d_in[31];
    float* out = (float*)d_out;

    float *pq,*pk,*pv,*pm,*px2,*py,*pyi,*pqs,*pqt,*pks,*pkt,*pvv,*ptsc,*pssc;
    float *py2sr,*py2s,*py2e,*py2,*pz,*pffh,*pffo,*pselw;
    int *pselidx,*pselcnt;
    cudaGetSymbolAddress((void**)&pq, g_q);
    cudaGetSymbolAddress((void**)&pk, g_k);
    cudaGetSymbolAddress((void**)&pv, g_v);
    cudaGetSymbolAddress((void**)&pm, g_merged);
    cudaGetSymbolAddress((void**)&px2, g_x2);
    cudaGetSymbolAddress((void**)&py, g_y);
    cudaGetSymbolAddress((void**)&pyi, g_yi);
    cudaGetSymbolAddress((void**)&pqs, g_qs);
    cudaGetSymbolAddress((void**)&pqt, g_qt);
    cudaGetSymbolAddress((void**)&pks, g_ksf);
    cudaGetSymbolAddress((void**)&pkt, g_kt);
    cudaGetSymbolAddress((void**)&pvv, g_vv);
    cudaGetSymbolAddress((void**)&ptsc, g_tsc);
    cudaGetSymbolAddress((void**)&pssc, g_ssc);
    cudaGetSymbolAddress((void**)&pselw, g_selw);
    cudaGetSymbolAddress((void**)&pselidx, g_selidx);
    cudaGetSymbolAddress((void**)&pselcnt, g_selcnt);
    cudaGetSymbolAddress((void**)&py2sr, g_y2s_raw);
    cudaGetSymbolAddress((void**)&py2s, g_y2s);
    cudaGetSymbolAddress((void**)&py2e, g_y2e);
    cudaGetSymbolAddress((void**)&py2, g_y2);
    cudaGetSymbolAddress((void**)&pz, g_z);
    cudaGetSymbolAddress((void**)&pffh, g_ffh);
    cudaGetSymbolAddress((void**)&pffo, g_ffo);

    const int FL_SMEM  = 114176;
    const int SM_BF    = 81920;   // 8 * 128*20 words * 4 B
    cudaFuncSetAttribute(flash_kernel<true>,  cudaFuncAttributeMaxDynamicSharedMemorySize, FL_SMEM);
    cudaFuncSetAttribute(flash_kernel<false>, cudaFuncAttributeMaxDynamicSharedMemorySize, FL_SMEM);
    cudaFuncSetAttribute(gemm_bf16<128,128,false>, cudaFuncAttributeMaxDynamicSharedMemorySize, SM_BF);
    cudaFuncSetAttribute(gemm_bf16<128,128,true>,  cudaFuncAttributeMaxDynamicSharedMemorySize, SM_BF);

    auto GB = [&](const float* A, const float* Bm, float* C, int M, int Nn, int K,
                  const float* bias, int act){
        dim3 grid((Nn + 127)/128, (M + 127)/128, 1);
        gemm_bf16<128,128,false><<<grid, 256, SM_BF>>>(A, Bm, C, M, Nn, K, K, Nn, Nn, 1,
                                                       0,0,0,0,0,0, bias, 1.f, act);
    };

    // ---- self attention (all 3xBF16) ----
    GB(x, Wq1, pq, BT, DD, DD, nullptr, 0);
    GB(x, Wk1, pk, BT, DD, DD, nullptr, 0);
    GB(x, Wv1, pv, BT, DD, DD, nullptr, 0);
    flash_kernel<true><<<dim3(TT/128, BB*HH), 256, FL_SMEM>>>(pq, pk, pv, pm, TT, nullptr, 0.125f);
    GB(pm, Wo1, px2, BT, DD, DD, nullptr, 0);
    ln_kernel<<<BT, 256>>>(x, px2, 1.f, w_g1, w_be1, py);

    // ---- selective hierarchical top-k ----
    concat_kernel<<<(BT*DCc + 255)/256, 256>>>(py, intent, pyi);
    GB(pyi, Wq_stat, pqs, BT, DD, DCc, nullptr, 0);
    GB(pyi, Wq_token, pqt, BT, DD, DCc, nullptr, 0);
    GB(stat_ft, Wk_stat, pks, BB*SSt, DD, DD, nullptr, 0);
    GB(stat_enc, Wk_token, pkt, BSN, DD, DD, nullptr, 0);
    GB(stat_enc, Wv_sel, pvv, BSN, DD, DD, nullptr, 0);
    ssc_kernel<<<BT, 256>>>(pqs, pks, pssc);
    gemm_bf16<128,128,true><<<dim3((SSt*NNtk)/128, TT/128, BB), 256, SM_BF>>>(
        pqt, pkt, ptsc, TT, SSt*NNtk, DD, DD, DD, SSt*NNtk, 1,
        (size_t)TT*DD, 0, (size_t)SSt*NNtk*DD, 0,
        (size_t)TT*SSt*NNtk, 0, nullptr, 1.f/32.f, 0);
    sel_topk_kernel<<<BT, 512>>>(pssc, ptsc, svl, pselidx, pselw, pselcnt);
    gather_y2s_kernel<<<BT, 256>>>(pselidx, pselw, pselcnt, pvv, py2sr);
    GB(py2sr, Wo_sel, py2s, BT, DD, DD, nullptr, 0);

    // ---- exemplar cross attention ----
    GB(pyi, Wq2, pq, BT, DD, DCc, nullptr, 0);
    GB(ex, Wk2, pk, BB*EEx, DD, DD, nullptr, 0);
    GB(ex, Wv2, pv, BB*EEx, DD, DD, nullptr, 0);
    flash_kernel<false><<<dim3(TT/128, BB*HH), 256, FL_SMEM>>>(pq, pk, pv, pm, EEx, evl, 0.125f);
    GB(pm, Wo2, py2e, BT, DD, DD, nullptr, 0);

    // ---- gate, LN, FFN, LN ----
    gate_kernel<<<BT, 256>>>(py2s, py2e, Wg, py2);
    ln_kernel<<<BT, 256>>>(py, py2, 2.f, w_g2, w_be2, pz);
    GB(pz, W1, pffh, BT, DFFf, DD, b1, 1);
    GB(pffh, W2, pffo, BT, DD, DFFf, b2, 0);
    ln_kernel<<<BT, 256>>>(pz, pffo, 1.f, w_g3, w_be3, out);
}

// round 16
// speedup vs baseline: 1.8315x; 1.8315x over previous
#include <cuda_runtime.h>
#include <cuda_bf16.h>
#include <math.h>

#define BB   4
#define TT   1024
#define DD   1024
#define DIi  256
#define DCc  1280
#define DFFf 4096
#define HH   16
#define DHh  64
#define SSt  16
#define NNtk 256
#define EEx  1024
#define BT   (BB*TT)            /* 4096  */
#define BSN  (BB*SSt*NNtk)      /* 16384 */
#define NEGV -1e6f
#define FLW  36

typedef unsigned short ushortt;

// ---------------- scratch ----------------
__device__ float g_q[BT*DD];
__device__ float g_k[BT*DD];
__device__ float g_v[BT*DD];
__device__ float g_merged[BT*DD];
__device__ float g_x2[BT*DD];
__device__ float g_y[BT*DD];
__device__ float g_yi[BT*DCc];
__device__ float g_qs[BT*DD];
__device__ float g_qt[BT*DD];
__device__ float g_ksf[BB*SSt*DD];
__device__ float g_kt[(size_t)BSN*DD];
__device__ float g_vv[(size_t)BSN*DD];
__device__ float g_tsc[(size_t)BT*SSt*NNtk];
__device__ float g_ssc[BT*SSt];
__device__ int   g_selidx[BT*128];
__device__ float g_selw[BT*128];
__device__ int   g_selcnt[BT];
__device__ float g_y2s_raw[BT*DD];
__device__ float g_y2s[BT*DD];
__device__ float g_y2e[BT*DD];
__device__ float g_y2[BT*DD];
__device__ float g_z[BT*DD];
__device__ float g_ffh[(size_t)BT*DFFf];
__device__ float g_ffo[BT*DD];
__device__ ushortt g_wh[25000000];   // pre-split weight hi planes, [n][k]
__device__ ushortt g_wl[25000000];   // pre-split weight lo planes, [n][k]

// ---------------- helpers ----------------
__device__ __forceinline__ void mma_bf16(float c[4], const unsigned a[4], unsigned b0, unsigned b1){
    asm volatile("mma.sync.aligned.m16n8k16.row.col.f32.bf16.bf16.f32 "
        "{%0,%1,%2,%3},{%4,%5,%6,%7},{%8,%9},{%0,%1,%2,%3};\n"
        : "+f"(c[0]), "+f"(c[1]), "+f"(c[2]), "+f"(c[3])
        : "r"(a[0]), "r"(a[1]), "r"(a[2]), "r"(a[3]), "r"(b0), "r"(b1));
}
__device__ __forceinline__ void split_bf2(float a, float b, unsigned& hi, unsigned& lo){
    __nv_bfloat16 ha = __float2bfloat16(a);
    __nv_bfloat16 hb = __float2bfloat16(b);
    __nv_bfloat16 la = __float2bfloat16(a - __bfloat162float(ha));
    __nv_bfloat16 lb = __float2bfloat16(b - __bfloat162float(hb));
    hi = (unsigned)__bfloat16_as_ushort(ha) | ((unsigned)__bfloat16_as_ushort(hb) << 16);
    lo = (unsigned)__bfloat16_as_ushort(la) | ((unsigned)__bfloat16_as_ushort(lb) << 16);
}
__device__ __forceinline__ void split_bf1(float a, ushortt& hi, ushortt& lo){
    __nv_bfloat16 h = __float2bfloat16(a);
    __nv_bfloat16 l = __float2bfloat16(a - __bfloat162float(h));
    hi = __bfloat16_as_ushort(h);
    lo = __bfloat16_as_ushort(l);
}
__device__ __forceinline__ float warpRedSum(float v){
#pragma unroll
    for (int o = 16; o > 0; o >>= 1) v += __shfl_xor_sync(0xffffffffu, v, o);
    return v;
}
__device__ __forceinline__ float blockSum(float v, float* sh){
    int lane = threadIdx.x & 31, w = threadIdx.x >> 5;
    v = warpRedSum(v);
    if (lane == 0) sh[w] = v;
    __syncthreads();
    if (w == 0){
        int nw = blockDim.x >> 5;
        float r = (lane < nw) ? sh[lane] : 0.f;
        r = warpRedSum(r);
        if (lane == 0) sh[0] = r;
    }
    __syncthreads();
    float r = sh[0];
    __syncthreads();
    return r;
}

// ============ weight pack: W[K,N] fp32 -> WH/WL [N,K] bf16 planes ============
__global__ void pack_w(const float* __restrict__ W, ushortt* __restrict__ WH,
                       ushortt* __restrict__ WL, int K, int N)
{
    __shared__ float t[32][33];
    int k0 = blockIdx.y*32, n0 = blockIdx.x*32;
    int tx = threadIdx.x, ty = threadIdx.y;   // 32 x 8
#pragma unroll
    for (int j = 0; j < 4; j++)
        t[ty + j*8][tx] = W[(size_t)(k0 + ty + j*8)*N + n0 + tx];
    __syncthreads();
#pragma unroll
    for (int j = 0; j < 4; j++){
        float v = t[tx][ty + j*8];
        ushortt h, l;
        split_bf1(v, h, l);
        size_t idx = (size_t)(n0 + ty + j*8)*K + k0 + tx;
        WH[idx] = h;
        WL[idx] = l;
    }
}

// ================= fused flash attention (3xBF16 QK^T and PV) =================
template<bool CAUSAL>
__global__ void __launch_bounds__(256)
flash_kernel(const float* __restrict__ Qg, const float* __restrict__ Kg,
             const float* __restrict__ Vg, float* __restrict__ Og,
             int Tk, const int* __restrict__ evl, float scale)
{
    extern __shared__ unsigned sm[];
    unsigned* QH = sm;
    unsigned* QL = sm + 4608;
    unsigned* KH = sm + 9216;
    unsigned* KL = sm + 11520;
    unsigned* VH = sm + 13824;
    unsigned* VL = sm + 16128;
    unsigned* PH = sm + 18432;
    unsigned* PL = sm + 23040;
    float* m_s  = (float*)(sm + 27648);
    float* l_s  = (float*)(sm + 27776);
    float* al_s = (float*)(sm + 27904);
    float* red0 = (float*)(sm + 28032);
    float* red1 = (float*)(sm + 28288);

    int bh = blockIdx.y;
    int b = bh / HH, h = bh % HH;
    int q0 = blockIdx.x * 128;
    const float* Qb = Qg + (size_t)b*TT*DD + h*DHh;
    const float* Kb = Kg + (size_t)b*Tk*DD + h*DHh;
    const float* Vb = Vg + (size_t)b*Tk*DD + h*DHh;
    float*       Ob = Og + (size_t)b*TT*DD + h*DHh;

    int tid = threadIdx.x, lane = tid & 31, wid = tid >> 5;
    int wm = wid >> 1, wn = wid & 1;
    int g = lane >> 2, tg = lane & 3;

#pragma unroll
    for (int v = 0; v < 8; v++){
        int idx = tid + v*256;
        int r = idx >> 4, f4 = idx & 15;
        float4 qv = *(const float4*)(Qb + (size_t)(q0+r)*DD + f4*4);
        split_bf2(qv.x, qv.y, QH[r*FLW + f4*2],   QL[r*FLW + f4*2]);
        split_bf2(qv.z, qv.w, QH[r*FLW + f4*2+1], QL[r*FLW + f4*2+1]);
    }
    if (tid < 128){ m_s[tid] = -1e30f; l_s[tid] = 0.f; }

    float oacc[2][4][4] = {};

    int vl = CAUSAL ? Tk : evl[b];
    int nkt = CAUSAL ? (q0/64 + 2) : ((vl + 63) >> 6);

    __syncthreads();

    for (int kt = 0; kt < nkt; kt++){
        int k0 = kt * 64;
#pragma unroll
        for (int v = 0; v < 4; v++){
            int idx = tid + v*256;
            int r = idx >> 4, f4 = idx & 15;
            float4 kv = *(const float4*)(Kb + (size_t)(k0+r)*DD + f4*4);
            split_bf2(kv.x, kv.y, KH[r*FLW + f4*2],   KL[r*FLW + f4*2]);
            split_bf2(kv.z, kv.w, KH[r*FLW + f4*2+1], KL[r*FLW + f4*2+1]);
            float4 vv = *(const float4*)(Vb + (size_t)(k0+r)*DD + f4*4);
            float fv[4] = {vv.x, vv.y, vv.z, vv.w};
#pragma unroll
            for (int j = 0; j < 4; j++){
                ushortt hh, ll;
                split_bf1(fv[j], hh, ll);
                int col = f4*4 + j;
                ((ushortt*)&VH[col*FLW + (r>>1)])[r&1] = hh;
                ((ushortt*)&VL[col*FLW + (r>>1)])[r&1] = ll;
            }
        }
        __syncthreads();

        float sacc[2][4][4] = {};
#pragma unroll
        for (int ks = 0; ks < 4; ks++){
            unsigned aH[2][4], aL[2][4];
#pragma unroll
            for (int mt = 0; mt < 2; mt++){
                int mr = wm*32 + mt*16;
                aH[mt][0] = QH[(mr+g)*FLW + ks*8+tg];
                aH[mt][1] = QH[(mr+g+8)*FLW + ks*8+tg];
                aH[mt][2] = QH[(mr+g)*FLW + ks*8+4+tg];
                aH[mt][3] = QH[(mr+g+8)*FLW + ks*8+4+tg];
                aL[mt][0] = QL[(mr+g)*FLW + ks*8+tg];
                aL[mt][1] = QL[(mr+g+8)*FLW + ks*8+tg];
                aL[mt][2] = QL[(mr+g)*FLW + ks*8+4+tg];
                aL[mt][3] = QL[(mr+g+8)*FLW + ks*8+4+tg];
            }
#pragma unroll
            for (int nt = 0; nt < 4; nt++){
                int nc = wn*32 + nt*8;
                unsigned bh0 = KH[(nc+g)*FLW + ks*8+tg];
                unsigned bh1 = KH[(nc+g)*FLW + ks*8+4+tg];
                unsigned bl0 = KL[(nc+g)*FLW + ks*8+tg];
                unsigned bl1 = KL[(nc+g)*FLW + ks*8+4+tg];
#pragma unroll
                for (int mt = 0; mt < 2; mt++){
                    mma_bf16(sacc[mt][nt], aH[mt], bl0, bl1);
                    mma_bf16(sacc[mt][nt], aL[mt], bh0, bh1);
                    mma_bf16(sacc[mt][nt], aH[mt], bh0, bh1);
                }
            }
        }

        float rmax[2][2] = {{-1e30f,-1e30f},{-1e30f,-1e30f}};
#pragma unroll
        for (int mt = 0; mt < 2; mt++){
            int r0 = q0 + wm*32 + mt*16 + g;
#pragma unroll
            for (int nt = 0; nt < 4; nt++){
                int c0 = k0 + wn*32 + nt*8 + 2*tg;
#pragma unroll
                for (int i = 0; i < 4; i++){
                    int rr = r0 + ((i>=2)?8:0);
                    int cc = c0 + (i&1);
                    bool ok = CAUSAL ? (cc <= rr) : (cc < vl);
                    float sv = ok ? sacc[mt][nt][i]*scale : -1e30f;
                    sacc[mt][nt][i] = sv;
                    rmax[mt][i>>1] = fmaxf(rmax[mt][i>>1], sv);
                }
            }
#pragma unroll
            for (int hf = 0; hf < 2; hf++){
                float v = rmax[mt][hf];
                v = fmaxf(v, __shfl_xor_sync(0xffffffffu, v, 1));
                v = fmaxf(v, __shfl_xor_sync(0xffffffffu, v, 2));
                rmax[mt][hf] = v;
            }
        }
        if (tg == 0){
#pragma unroll
            for (int mt = 0; mt < 2; mt++){
                red0[wn*128 + wm*32 + mt*16 + g]     = rmax[mt][0];
                red0[wn*128 + wm*32 + mt*16 + g + 8] = rmax[mt][1];
            }
        }
        __syncthreads();
        if (tid < 128){
            float t = fmaxf(red0[tid], red0[128+tid]);
            float mo = m_s[tid];
            float mn = fmaxf(mo, t);
            al_s[tid] = __expf(mo - mn);
            m_s[tid] = mn;
        }
        __syncthreads();

        float rsum[2][2] = {};
#pragma unroll
        for (int mt = 0; mt < 2; mt++){
            int lr0 = wm*32 + mt*16 + g;
            float mn0 = m_s[lr0], mn1 = m_s[lr0+8];
#pragma unroll
            for (int nt = 0; nt < 4; nt++){
                float p0 = __expf(sacc[mt][nt][0] - mn0);
                float p1 = __expf(sacc[mt][nt][1] - mn0);
                float p2 = __expf(sacc[mt][nt][2] - mn1);
                float p3 = __expf(sacc[mt][nt][3] - mn1);
                rsum[mt][0] += p0 + p1;
                rsum[mt][1] += p2 + p3;
                int w0 = wn*16 + nt*4 + tg;
                split_bf2(p0, p1, PH[lr0*FLW + w0],     PL[lr0*FLW + w0]);
                split_bf2(p2, p3, PH[(lr0+8)*FLW + w0], PL[(lr0+8)*FLW + w0]);
            }
#pragma unroll
            for (int hf = 0; hf < 2; hf++){
                float v = rsum[mt][hf];
                v += __shfl_xor_sync(0xffffffffu, v, 1);
                v += __shfl_xor_sync(0xffffffffu, v, 2);
                rsum[mt][hf] = v;
            }
            float a0 = al_s[lr0], a1 = al_s[lr0+8];
#pragma unroll
            for (int nt = 0; nt < 4; nt++){
                oacc[mt][nt][0] *= a0; oacc[mt][nt][1] *= a0;
                oacc[mt][nt][2] *= a1; oacc[mt][nt][3] *= a1;
            }
        }
        if (tg == 0){
#pragma unroll
            for (int mt = 0; mt < 2; mt++){
                red1[wn*128 + wm*32 + mt*16 + g]     = rsum[mt][0];
                red1[wn*128 + wm*32 + mt*16 + g + 8] = rsum[mt][1];
            }
        }
        __syncthreads();
        if (tid < 128)
            l_s[tid] = l_s[tid]*al_s[tid] + red1[tid] + red1[128+tid];

#pragma unroll
        for (int ks = 0; ks < 4; ks++){
            unsigned aH[2][4], aL[2][4];
#pragma unroll
            for (int mt = 0; mt < 2; mt++){
                int mr = wm*32 + mt*16;
                aH[mt][0] = PH[(mr+g)*FLW + ks*8+tg];
                aH[mt][1] = PH[(mr+g+8)*FLW + ks*8+tg];
                aH[mt][2] = PH[(mr+g)*FLW + ks*8+4+tg];
                aH[mt][3] = PH[(mr+g+8)*FLW + ks*8+4+tg];
                aL[mt][0] = PL[(mr+g)*FLW + ks*8+tg];
                aL[mt][1] = PL[(mr+g+8)*FLW + ks*8+tg];
                aL[mt][2] = PL[(mr+g)*FLW + ks*8+4+tg];
                aL[mt][3] = PL[(mr+g+8)*FLW + ks*8+4+tg];
            }
#pragma unroll
            for (int nt = 0; nt < 4; nt++){
                int nc = wn*32 + nt*8;
                unsigned bh0 = VH[(nc+g)*FLW + ks*8+tg];
                unsigned bh1 = VH[(nc+g)*FLW + ks*8+4+tg];
                unsigned bl0 = VL[(nc+g)*FLW + ks*8+tg];
                unsigned bl1 = VL[(nc+g)*FLW + ks*8+4+tg];
#pragma unroll
                for (int mt = 0; mt < 2; mt++){
                    mma_bf16(oacc[mt][nt], aH[mt], bl0, bl1);
                    mma_bf16(oacc[mt][nt], aL[mt], bh0, bh1);
                    mma_bf16(oacc[mt][nt], aH[mt], bh0, bh1);
                }
            }
        }
        __syncthreads();
    }

#pragma unroll
    for (int mt = 0; mt < 2; mt++){
        int lr0 = wm*32 + mt*16 + g;
        float il0 = 1.f / l_s[lr0];
        float il1 = 1.f / l_s[lr0+8];
#pragma unroll
        for (int nt = 0; nt < 4; nt++){
            int c = wn*32 + nt*8 + 2*tg;
            Ob[(size_t)(q0+lr0)*DD + c]     = oacc[mt][nt][0]*il0;
            Ob[(size_t)(q0+lr0)*DD + c+1]   = oacc[mt][nt][1]*il0;
            Ob[(size_t)(q0+lr0+8)*DD + c]   = oacc[mt][nt][2]*il1;
            Ob[(size_t)(q0+lr0+8)*DD + c+1] = oacc[mt][nt][3]*il1;
        }
    }
}

// ===== 3xBF16 GEMM, pre-packed weight B ([N,K] bf16 planes), 2-stage pipeline ====
__global__ void __launch_bounds__(256, 2)
gemm_bf16_pw(const float* __restrict__ A, const ushortt* __restrict__ BH,
             const ushortt* __restrict__ BL, float* __restrict__ C,
             int M, int N, int K,
             const float* __restrict__ bias, int act)
{
    constexpr int BKb = 16, AW = 12;
    constexpr int ASZ = 128*AW, BSZ = 128*AW;

    extern __shared__ unsigned dsm[];
    unsigned* AsH = dsm;
    unsigned* AsL = dsm + 2*ASZ;
    unsigned* BsH = dsm + 4*ASZ;
    unsigned* BsL = dsm + 4*ASZ + 2*BSZ;

    int tid = threadIdx.x, lane = tid & 31, wid = tid >> 5;
    int wn = wid % 4, wm = wid / 4;
    int row0 = blockIdx.y * 128, col0 = blockIdx.x * 128;
    int g = lane >> 2, tg = lane & 3;

    float acc[4][4][4] = {};
    float4 ra[2];
    uint4  rbh, rbl;
    int nB = col0 + (tid >> 1), hB = (tid & 1);

    auto fetchA = [&](int kk){
#pragma unroll
        for (int v = 0; v < 2; v++){
            int i = tid + v*256;
            int r = i >> 2, c = (i & 3) * 4;
            int gr = row0 + r;
            ra[v] = (gr < M) ? *(const float4*)(A + (size_t)gr*K + kk + c)
                             : make_float4(0.f,0.f,0.f,0.f);
        }
    };
    auto storeA = [&](int st){
        unsigned* aH = AsH + st*ASZ;
        unsigned* aL = AsL + st*ASZ;
#pragma unroll
        for (int v = 0; v < 2; v++){
            int i = tid + v*256;
            int r = i >> 2, c2 = (i & 3) * 2;
            split_bf2(ra[v].x, ra[v].y, aH[r*AW+c2],   aL[r*AW+c2]);
            split_bf2(ra[v].z, ra[v].w, aH[r*AW+c2+1], aL[r*AW+c2+1]);
        }
    };
    auto fetchB = [&](int kk){
        const ushortt* pH = BH + (size_t)nB*K + kk + hB*8;
        const ushortt* pL = BL + (size_t)nB*K + kk + hB*8;
        rbh = *(const uint4*)pH;
        rbl = *(const uint4*)pL;
    };
    auto storeB = [&](int st){
        unsigned* bH = BsH + st*BSZ + (tid>>1)*AW + hB*4;
        unsigned* bL = BsL + st*BSZ + (tid>>1)*AW + hB*4;
        bH[0] = rbh.x; bH[1] = rbh.y; bH[2] = rbh.z; bH[3] = rbh.w;
        bL[0] = rbl.x; bL[1] = rbl.y; bL[2] = rbl.z; bL[3] = rbl.w;
    };

    fetchA(0); fetchB(0);
    storeA(0); storeB(0);
    __syncthreads();

    int kiters = K / BKb;
    for (int kt = 0; kt < kiters; kt++){
        int st = kt & 1;
        bool more = (kt + 1 < kiters);
        if (more){ fetchA((kt+1)*BKb); fetchB((kt+1)*BKb); }
        const unsigned* aH = AsH + st*ASZ;
        const unsigned* aL = AsL + st*ASZ;
        const unsigned* bHs = BsH + st*BSZ;
        const unsigned* bLs = BsL + st*BSZ;
        {
            unsigned afH[4][4], afL[4][4];
#pragma unroll
            for (int mt = 0; mt < 4; mt++){
                int mr = wm*64 + mt*16;
                afH[mt][0] = aH[(mr+g  )*AW + tg  ];
                afH[mt][1] = aH[(mr+g+8)*AW + tg  ];
                afH[mt][2] = aH[(mr+g  )*AW + tg+4];
                afH[mt][3] = aH[(mr+g+8)*AW + tg+4];
                afL[mt][0] = aL[(mr+g  )*AW + tg  ];
                afL[mt][1] = aL[(mr+g+8)*AW + tg  ];
                afL[mt][2] = aL[(mr+g  )*AW + tg+4];
                afL[mt][3] = aL[(mr+g+8)*AW + tg+4];
            }
#pragma unroll
            for (int nt = 0; nt < 4; nt++){
                int nc = wn*32 + nt*8;
                unsigned bh0 = bHs[(nc+g)*AW + tg], bh1 = bHs[(nc+g)*AW + tg+4];
                unsigned bl0 = bLs[(nc+g)*AW + tg], bl1 = bLs[(nc+g)*AW + tg+4];
#pragma unroll
                for (int mt = 0; mt < 4; mt++){
                    mma_bf16(acc[mt][nt], afH[mt], bl0, bl1);
                    mma_bf16(acc[mt][nt], afL[mt], bh0, bh1);
                    mma_bf16(acc[mt][nt], afH[mt], bh0, bh1);
                }
            }
        }
        if (more){
            storeA(st ^ 1); storeB(st ^ 1);
            __syncthreads();
        }
    }

#pragma unroll
    for (int mt = 0; mt < 4; mt++){
#pragma unroll
        for (int nt = 0; nt < 4; nt++){
            int r  = row0 + wm*64 + mt*16 + g;
            int c  = col0 + wn*32 + nt*8 + 2*tg;
            float b0 = bias ? bias[c]   : 0.f;
            float b1 = bias ? bias[c+1] : 0.f;
            if (r < M){
                float v0 = acc[mt][nt][0] + b0;
                float v1 = acc[mt][nt][1] + b1;
                if (act){ v0 = fmaxf(v0,0.f); v1 = fmaxf(v1,0.f); }
                C[(size_t)r*N + c]   = v0;
                C[(size_t)r*N + c+1] = v1;
            }
            int r2 = r + 8;
            if (r2 < M){
                float v2 = acc[mt][nt][2] + b0;
                float v3 = acc[mt][nt][3] + b1;
                if (act){ v2 = fmaxf(v2,0.f); v3 = fmaxf(v3,0.f); }
                C[(size_t)r2*N + c]   = v2;
                C[(size_t)r2*N + c+1] = v3;
            }
        }
    }
}

// ===== 3xBF16 GEMM, TRANSB activation B (for tsc), 2-stage pipeline (R13/R14) ===
__global__ void __launch_bounds__(256, 2)
gemm_bf16_tb(const float* __restrict__ A, const float* __restrict__ B, float* __restrict__ C,
             int M, int N, int K, int lda, int ldb, int ldc,
             size_t sAb, size_t sBb, size_t sCb, float scale)
{
    constexpr int BKb = 16, AW = 12;
    constexpr int ASZ = 128*AW, BSZ = 128*AW;

    extern __shared__ unsigned dsm[];
    unsigned* AsH = dsm;
    unsigned* AsL = dsm + 2*ASZ;
    unsigned* BsH = dsm + 4*ASZ;
    unsigned* BsL = dsm + 4*ASZ + 2*BSZ;

    int z = blockIdx.z;
    const float* Ab = A + (size_t)z*sAb;
    const float* Bb = B + (size_t)z*sBb;
    float*       Cb = C + (size_t)z*sCb;

    int tid = threadIdx.x, lane = tid & 31, wid = tid >> 5;
    int wn = wid % 4, wm = wid / 4;
    int row0 = blockIdx.y * 128, col0 = blockIdx.x * 128;
    int g = lane >> 2, tg = lane & 3;

    float acc[4][4][4] = {};
    float4 ra[2], rb[2];

    auto fetchA = [&](int kk){
#pragma unroll
        for (int v = 0; v < 2; v++){
            int i = tid + v*256;
            int r = i >> 2, c = (i & 3) * 4;
            int gr = row0 + r;
            ra[v] = (gr < M) ? *(const float4*)(Ab + (size_t)gr*lda + kk + c)
                             : make_float4(0.f,0.f,0.f,0.f);
        }
    };
    auto storeA = [&](int st){
        unsigned* aH = AsH + st*ASZ;
        unsigned* aL = AsL + st*ASZ;
#pragma unroll
        for (int v = 0; v < 2; v++){
            int i = tid + v*256;
            int r = i >> 2, c2 = (i & 3) * 2;
            split_bf2(ra[v].x, ra[v].y, aH[r*AW+c2],   aL[r*AW+c2]);
            split_bf2(ra[v].z, ra[v].w, aH[r*AW+c2+1], aL[r*AW+c2+1]);
        }
    };
    auto fetchB = [&](int kk){
#pragma unroll
        for (int v = 0; v < 2; v++){
            int i = tid + v*256;
            int r = i >> 2, c = (i & 3) * 4;
            int gr = col0 + r;
            rb[v] = (gr < N) ? *(const float4*)(Bb + (size_t)gr*ldb + kk + c)
                             : make_float4(0.f,0.f,0.f,0.f);
        }
    };
    auto storeB = [&](int st){
        unsigned* bH = BsH + st*BSZ;
        unsigned* bL = BsL + st*BSZ;
#pragma unroll
        for (int v = 0; v < 2; v++){
            int i = tid + v*256;
            int r = i >> 2, c2 = (i & 3) * 2;
            split_bf2(rb[v].x, rb[v].y, bH[r*AW+c2],   bL[r*AW+c2]);
            split_bf2(rb[v].z, rb[v].w, bH[r*AW+c2+1], bL[r*AW+c2+1]);
        }
    };

    fetchA(0); fetchB(0);
    storeA(0); storeB(0);
    __syncthreads();

    int kiters = K / BKb;
    for (int kt = 0; kt < kiters; kt++){
        int st = kt & 1;
        bool more = (kt + 1 < kiters);
        if (more){ fetchA((kt+1)*BKb); fetchB((kt+1)*BKb); }
        const unsigned* aH = AsH + st*ASZ;
        const unsigned* aL = AsL + st*ASZ;
        const unsigned* bHs = BsH + st*BSZ;
        const unsigned* bLs = BsL + st*BSZ;
        {
            unsigned afH[4][4], afL[4][4];
#pragma unroll
            for (int mt = 0; mt < 4; mt++){
                int mr = wm*64 + mt*16;
                afH[mt][0] = aH[(mr+g  )*AW + tg  ];
                afH[mt][1] = aH[(mr+g+8)*AW + tg  ];
                afH[mt][2] = aH[(mr+g  )*AW + tg+4];
                afH[mt][3] = aH[(mr+g+8)*AW + tg+4];
                afL[mt][0] = aL[(mr+g  )*AW + tg  ];
                afL[mt][1] = aL[(mr+g+8)*AW + tg  ];
                afL[mt][2] = aL[(mr+g  )*AW + tg+4];
                afL[mt][3] = aL[(mr+g+8)*AW + tg+4];
            }
#pragma unroll
            for (int nt = 0; nt < 4; nt++){
                int nc = wn*32 + nt*8;
                unsigned bh0 = bHs[(nc+g)*AW + tg], bh1 = bHs[(nc+g)*AW + tg+4];
                unsigned bl0 = bLs[(nc+g)*AW + tg], bl1 = bLs[(nc+g)*AW + tg+4];
#pragma unroll
                for (int mt = 0; mt < 4; mt++){
                    mma_bf16(acc[mt][nt], afH[mt], bl0, bl1);
                    mma_bf16(acc[mt][nt], afL[mt], bh0, bh1);
                    mma_bf16(acc[mt][nt], afH[mt], bh0, bh1);
                }
            }
        }
        if (more){
            storeA(st ^ 1); storeB(st ^ 1);
            __syncthreads();
        }
    }

#pragma unroll
    for (int mt = 0; mt < 4; mt++){
#pragma unroll
        for (int nt = 0; nt < 4; nt++){
            int r  = row0 + wm*64 + mt*16 + g;
            int c  = col0 + wn*32 + nt*8 + 2*tg;
            if (r < M && c < N){
                Cb[(size_t)r*ldc + c]   = acc[mt][nt][0]*scale;
                Cb[(size_t)r*ldc + c+1] = acc[mt][nt][1]*scale;
            }
            int r2 = r + 8;
            if (r2 < M && c < N){
                Cb[(size_t)r2*ldc + c]   = acc[mt][nt][2]*scale;
                Cb[(size_t)r2*ldc + c+1] = acc[mt][nt][3]*scale;
            }
        }
    }
}

// ---------------- LN ----------------
__global__ void ln_kernel(const float* __restrict__ A, const float* __restrict__ Bm, float sB,
                          const float* __restrict__ gw, const float* __restrict__ bw,
                          float* __restrict__ Out)
{
    __shared__ float sh[32];
    int row = blockIdx.x;
    int tid = threadIdx.x;
    float4 a4 = *(const float4*)(A + (size_t)row*DD + tid*4);
    float x[4] = {a4.x, a4.y, a4.z, a4.w};
    if (Bm){
        float4 b4 = *(const float4*)(Bm + (size_t)row*DD + tid*4);
        x[0] += sB*b4.x; x[1] += sB*b4.y; x[2] += sB*b4.z; x[3] += sB*b4.w;
    }
    float s = x[0]+x[1]+x[2]+x[3];
    s = blockSum(s, sh);
    float mean = s * (1.f/DD);
    float q = 0.f;
#pragma unroll
    for (int i = 0; i < 4; i++){ float d = x[i]-mean; q += d*d; }
    q = blockSum(q, sh);
    float rstd = rsqrtf(q * (1.f/DD) + 1e-5f);
#pragma unroll
    for (int i = 0; i < 4; i++){
        int c = tid*4 + i;
        Out[(size_t)row*DD + c] = (x[i]-mean)*rstd*gw[c] + bw[c];
    }
}

// ---------------- concat ----------------
__global__ void concat_kernel(const float* __restrict__ Y, const float* __restrict__ intent,
                              float* __restrict__ Yi)
{
    int i = blockIdx.x*blockDim.x + threadIdx.x;
    if (i >= BT*DCc) return;
    int row = i / DCc, c = i % DCc;
    float val;
    if (c < DD) val = Y[(size_t)row*DD + c];
    else { int b = row / TT; val = intent[b*DIi + (c - DD)]; }
    Yi[i] = val;
}

// ---------------- ssc ----------------
__global__ void ssc_kernel(const float* __restrict__ QS, const float* __restrict__ KS,
                           float* __restrict__ SSC)
{
    __shared__ float qsh[DD];
    int row = blockIdx.x;
    int b = row / TT;
    int tid = threadIdx.x;
    *(float4*)&qsh[tid*4] = *(const float4*)(QS + (size_t)row*DD + tid*4);
    __syncthreads();
    int w = tid >> 5, lane = tid & 31;
    for (int ss = w; ss < SSt; ss += 8){
        const float* kr = KS + ((size_t)b*SSt + ss)*DD;
        float sum = 0.f;
        for (int j = lane*4; j < DD; j += 128){
            float4 kv = *(const float4*)(kr + j);
            float4 qv = *(const float4*)&qsh[j];
            sum += qv.x*kv.x + qv.y*kv.y + qv.z*kv.z + qv.w*kv.w;
        }
        sum = warpRedSum(sum);
        if (lane == 0) SSC[row*SSt + ss] = sum * (1.f/32.f);
    }
}

// ---------------- topk select ----------------
__global__ void sel_topk_kernel(const float* __restrict__ SSC, const float* __restrict__ TSC,
                                const int* __restrict__ svl,
                                int* __restrict__ OutIdx, float* __restrict__ OutW,
                                int* __restrict__ OutCnt)
{
    __shared__ float s_v[SSt];
    __shared__ float s_sw[SSt];
    __shared__ int   s_rank[SSt];
    __shared__ float s_tv[SSt][16];
    __shared__ int   s_ti[SSt][16];
    int row = blockIdx.x;
    int b = row / TT;
    int tid = threadIdx.x;
    int w = tid >> 5, lane = tid & 31;
    if (tid < SSt){
        float val = SSC[row*SSt + tid];
        if (tid >= svl[b]) val = NEGV;
        s_v[tid] = val;
    }
    __syncthreads();
    if (tid < SSt){
        float myv = s_v[tid];
        int cnt = 0;
        float m = -3.4e38f;
#pragma unroll
        for (int j = 0; j < SSt; j++){
            float o = s_v[j];
            if (o > myv || (o == myv && j < tid)) cnt++;
            m = fmaxf(m, o);
        }
        s_sw[tid] = (cnt < 8) ? expf(myv - m) : 0.f;
    }
    __syncthreads();
    if (tid == 0){
        float den = 0.f;
        for (int j = 0; j < SSt; j++) den += s_sw[j];
        float inv = 1.f/den;
        int r = 0;
        for (int j = 0; j < SSt; j++){
            float swv = s_sw[j]*inv;
            s_sw[j] = swv;
            s_rank[j] = r;
            if (swv > 0.f) r++;
        }
        OutCnt[row] = r*16;
    }
    __syncthreads();
    float swv = s_sw[w];
    if (swv > 0.f){
        const float* tr = TSC + ((size_t)row*SSt + w)*NNtk;
        float vloc[8];
#pragma unroll
        for (int r2 = 0; r2 < 8; r2++) vloc[r2] = tr[r2*32 + lane];
        for (int it = 0; it < 16; it++){
            float bv = -3.4e38f; int bi = 1 << 30;
#pragma unroll
            for (int r2 = 0; r2 < 8; r2++){
                if (vloc[r2] > bv){ bv = vloc[r2]; bi = r2*32 + lane; }
            }
#pragma unroll
            for (int off = 16; off > 0; off >>= 1){
                float ov = __shfl_xor_sync(0xffffffffu, bv, off);
                int   oi = __shfl_xor_sync(0xffffffffu, bi, off);
                if (ov > bv || (ov == bv && oi < bi)){ bv = ov; bi = oi; }
            }
            if (lane == 0){ s_tv[w][it] = bv; s_ti[w][it] = bi; }
            if ((bi & 31) == lane) vloc[bi >> 5] = -3.4e38f;
        }
        __syncwarp();
        float m2 = s_tv[w][0];
        float e2 = (lane < 16) ? expf(s_tv[w][lane] - m2) : 0.f;
        float den2 = warpRedSum(e2);
        if (lane < 16){
            int base = s_rank[w]*16;
            OutW[row*128 + base + lane]   = swv * e2 / den2;
            OutIdx[row*128 + base + lane] = w*NNtk + s_ti[w][lane];
        }
    }
}

// ---------------- sparse gather y2s ----------------
__global__ void gather_y2s_kernel(const int* __restrict__ Idx, const float* __restrict__ Wt,
                                  const int* __restrict__ Cnt, const float* __restrict__ VV,
                                  float* __restrict__ Out)
{
    __shared__ int   sh_i[128];
    __shared__ float sh_w[128];
    int row = blockIdx.x;
    int b = row / TT;
    int tid = threadIdx.x;
    int cnt = Cnt[row];
    if (tid < 128){ sh_i[tid] = Idx[row*128 + tid]; sh_w[tid] = Wt[row*128 + tid]; }
    __syncthreads();
    const float* vb = VV + (size_t)b*SSt*NNtk*DD;
    float4 acc = make_float4(0.f,0.f,0.f,0.f);
    int c4 = tid*4;
    for (int e = 0; e < cnt; e++){
        float wv = sh_w[e];
        float4 x4 = *(const float4*)(vb + (size_t)sh_i[e]*DD + c4);
        acc.x += wv*x4.x; acc.y += wv*x4.y; acc.z += wv*x4.z; acc.w += wv*x4.w;
    }
    *(float4*)(Out + (size_t)row*DD + c4) = acc;
}

// ---------------- gate ----------------
__global__ void gate_kernel(const float* __restrict__ Y2S, const float* __restrict__ Y2E,
                            const float* __restrict__ Wg, float* __restrict__ Y2)
{
    __shared__ float sh[32];
    int row = blockIdx.x;
    int tid = threadIdx.x;
    int c4 = tid*4;
    float4 a  = *(const float4*)(Y2S + (size_t)row*DD + c4);
    float4 b4 = *(const float4*)(Y2E + (size_t)row*DD + c4);
    float4 w1 = *(const float4*)(Wg + c4);
    float4 w2 = *(const float4*)(Wg + DD + c4);
    float part = a.x*w1.x + a.y*w1.y + a.z*w1.z + a.w*w1.w
               + b4.x*w2.x + b4.y*w2.y + b4.z*w2.z + b4.w*w2.w;
    float dot = blockSum(part, sh);
    float gv = 1.f/(1.f + expf(-dot));
    float4 o;
    o.x = gv*a.x + (1.f-gv)*b4.x;
    o.y = gv*a.y + (1.f-gv)*b4.y;
    o.z = gv*a.z + (1.f-gv)*b4.z;
    o.w = gv*a.w + (1.f-gv)*b4.w;
    *(float4*)(Y2 + (size_t)row*DD + c4) = o;
}

// ---------------- launch ----------------
extern "C" void kernel_launch(void* const* d_in, const int* in_sizes, int n_in,
                              void* d_out, int out_size)
{
    const float* x        = (const float*)d_in[0];
    const float* stat_enc = (const float*)d_in[1];
    const float* ex       = (const float*)d_in[2];
    const float* stat_ft  = (const float*)d_in[3];
    const float* intent   = (const float*)d_in[4];
    const float* Wq1=(const float*)d_in[5],  *Wk1=(const float*)d_in[6];
    const float* Wv1=(const float*)d_in[7],  *Wo1=(const float*)d_in[8];
    const float* Wq_stat=(const float*)d_in[9],  *Wq_token=(const float*)d_in[10];
    const float* Wk_stat=(const float*)d_in[11], *Wk_token=(const float*)d_in[12];
    const float* Wv_sel=(const float*)d_in[13],  *Wo_sel=(const float*)d_in[14];
    const float* Wq2=(const float*)d_in[15], *Wk2=(const float*)d_in[16];
    const float* Wv2=(const float*)d_in[17], *Wo2=(const float*)d_in[18];
    const float* Wg=(const float*)d_in[19];
    const float* W1=(const float*)d_in[20], *b1=(const float*)d_in[21];
    const float* W2=(const float*)d_in[22], *b2=(const float*)d_in[23];
    const float* w_g1=(const float*)d_in[24], *w_be1=(const float*)d_in[25];
    const float* w_g2=(const float*)d_in[26], *w_be2=(const float*)d_in[27];
    const float* w_g3=(const float*)d_in[28], *w_be3=(const float*)d_in[29];
    const int* svl = (const int*)d_in[30];
    const int* evl = (const int*)d_in[31];
    float* out = (float*)d_out;

    float *pq,*pk,*pv,*pm,*px2,*py,*pyi,*pqs,*pqt,*pks,*pkt,*pvv,*ptsc,*pssc;
    float *py2sr,*py2s,*py2e,*py2,*pz,*pffh,*pffo,*pselw;
    int *pselidx,*pselcnt;
    ushortt *pwh, *pwl;
    cudaGetSymbolAddress((void**)&pq, g_q);
    cudaGetSymbolAddress((void**)&pk, g_k);
    cudaGetSymbolAddress((void**)&pv, g_v);
    cudaGetSymbolAddress((void**)&pm, g_merged);
    cudaGetSymbolAddress((void**)&px2, g_x2);
    cudaGetSymbolAddress((void**)&py, g_y);
    cudaGetSymbolAddress((void**)&pyi, g_yi);
    cudaGetSymbolAddress((void**)&pqs, g_qs);
    cudaGetSymbolAddress((void**)&pqt, g_qt);
    cudaGetSymbolAddress((void**)&pks, g_ksf);
    cudaGetSymbolAddress((void**)&pkt, g_kt);
    cudaGetSymbolAddress((void**)&pvv, g_vv);
    cudaGetSymbolAddress((void**)&ptsc, g_tsc);
    cudaGetSymbolAddress((void**)&pssc, g_ssc);
    cudaGetSymbolAddress((void**)&pselw, g_selw);
    cudaGetSymbolAddress((void**)&pselidx, g_selidx);
    cudaGetSymbolAddress((void**)&pselcnt, g_selcnt);
    cudaGetSymbolAddress((void**)&py2sr, g_y2s_raw);
    cudaGetSymbolAddress((void**)&py2s, g_y2s);
    cudaGetSymbolAddress((void**)&py2e, g_y2e);
    cudaGetSymbolAddress((void**)&py2, g_y2);
    cudaGetSymbolAddress((void**)&pz, g_z);
    cudaGetSymbolAddress((void**)&pffh, g_ffh);
    cudaGetSymbolAddress((void**)&pffo, g_ffo);
    cudaGetSymbolAddress((void**)&pwh, g_wh);
    cudaGetSymbolAddress((void**)&pwl, g_wl);

    const int FL_SMEM  = 114176;
    const int SM_BF    = 49152;
    cudaFuncSetAttribute(flash_kernel<true>,  cudaFuncAttributeMaxDynamicSharedMemorySize, FL_SMEM);
    cudaFuncSetAttribute(flash_kernel<false>, cudaFuncAttributeMaxDynamicSharedMemorySize, FL_SMEM);
    cudaFuncSetAttribute(gemm_bf16_pw, cudaFuncAttributeMaxDynamicSharedMemorySize, SM_BF);
    cudaFuncSetAttribute(gemm_bf16_tb, cudaFuncAttributeMaxDynamicSharedMemorySize, SM_BF);

    // ---- pack all weights into split-bf16 [N][K] planes ----
    size_t off = 0;
    struct WP { const ushortt *h, *l; };
    auto pack = [&](const float* W, int K, int N) -> WP {
        ushortt* dh = pwh + off;
        ushortt* dl = pwl + off;
        pack_w<<<dim3(N/32, K/32), dim3(32,8)>>>(W, dh, dl, K, N);
        off += (size_t)K*N;
        return { dh, dl };
    };
    WP wq1 = pack(Wq1, DD, DD),   wk1 = pack(Wk1, DD, DD);
    WP wv1 = pack(Wv1, DD, DD),   wo1 = pack(Wo1, DD, DD);
    WP wqs = pack(Wq_stat, DCc, DD), wqt = pack(Wq_token, DCc, DD);
    WP wks = pack(Wk_stat, DD, DD),  wkt = pack(Wk_token, DD, DD);
    WP wvs = pack(Wv_sel, DD, DD),   wos = pack(Wo_sel, DD, DD);
    WP wq2 = pack(Wq2, DCc, DD),  wk2 = pack(Wk2, DD, DD);
    WP wv2 = pack(Wv2, DD, DD),   wo2 = pack(Wo2, DD, DD);
    WP w1p = pack(W1, DD, DFFf),  w2p = pack(W2, DFFf, DD);

    auto GB = [&](const float* A, WP w, float* C, int M, int Nn, int K,
                  const float* bias, int act){
        dim3 grid(Nn/128, (M + 127)/128);
        gemm_bf16_pw<<<grid, 256, SM_BF>>>(A, w.h, w.l, C, M, Nn, K, bias, act);
    };

    // ---- self attention ----
    GB(x, wq1, pq, BT, DD, DD, nullptr, 0);
    GB(x, wk1, pk, BT, DD, DD, nullptr, 0);
    GB(x, wv1, pv, BT, DD, DD, nullptr, 0);
    flash_kernel<true><<<dim3(TT/128, BB*HH), 256, FL_SMEM>>>(pq, pk, pv, pm, TT, nullptr, 0.125f);
    GB(pm, wo1, px2, BT, DD, DD, nullptr, 0);
    ln_kernel<<<BT, 256>>>(x, px2, 1.f, w_g1, w_be1, py);

    // ---- selective hierarchical top-k ----
    concat_kernel<<<(BT*DCc + 255)/256, 256>>>(py, intent, pyi);
    GB(pyi, wqs, pqs, BT, DD, DCc, nullptr, 0);
    GB(pyi, wqt, pqt, BT, DD, DCc, nullptr, 0);
    GB(stat_ft, wks, pks, BB*SSt, DD, DD, nullptr, 0);
    GB(stat_enc, wkt, pkt, BSN, DD, DD, nullptr, 0);
    GB(stat_enc, wvs, pvv, BSN, DD, DD, nullptr, 0);
    ssc_kernel<<<BT, 256>>>(pqs, pks, pssc);
    gemm_bf16_tb<<<dim3((SSt*NNtk)/128, TT/128, BB), 256, SM_BF>>>(
        pqt, pkt, ptsc, TT, SSt*NNtk, DD, DD, DD, SSt*NNtk,
        (size_t)TT*DD, (size_t)SSt*NNtk*DD, (size_t)TT*SSt*NNtk, 1.f/32.f);
    sel_topk_kernel<<<BT, 512>>>(pssc, ptsc, svl, pselidx, pselw, pselcnt);
    gather_y2s_kernel<<<BT, 256>>>(pselidx, pselw, pselcnt, pvv, py2sr);
    GB(py2sr, wos, py2s, BT, DD, DD, nullptr, 0);

    // ---- exemplar cross attention ----
    GB(pyi, wq2, pq, BT, DD, DCc, nullptr, 0);
    GB(ex, wk2, pk, BB*EEx, DD, DD, nullptr, 0);
    GB(ex, wv2, pv, BB*EEx, DD, DD, nullptr, 0);
    flash_kernel<false><<<dim3(TT/128, BB*HH), 256, FL_SMEM>>>(pq, pk, pv, pm, EEx, evl, 0.125f);
    GB(pm, wo2, py2e, BT, DD, DD, nullptr, 0);

    // ---- gate, LN, FFN, LN ----
    gate_kernel<<<BT, 256>>>(py2s, py2e, Wg, py2);
    ln_kernel<<<BT, 256>>>(py, py2, 2.f, w_g2, w_be2, pz);
    GB(pz, w1p, pffh, BT, DFFf, DD, b1, 1);
    GB(pffh, w2p, pffo, BT, DD, DFFf, b2, 0);
    ln_kernel<<<BT, 256>>>(pz, pffo, 1.f, w_g3, w_be3, out);
}